// round 12
// baseline (speedup 1.0000x reference)
#include <cuda_runtime.h>
#include <cuda_bf16.h>
#include <cstdint>

#define BATCH 32
#define TSEQ  1024
#define DIN   256
#define UNITS 256
#define GC    2048   // 8*U total gate columns
#define G4    1024   // 4*U per direction
#define LDH   80     // padded hs row stride in bytes (32 bf16 = 64B data + 16B pad)

// ---------------- scratch (device globals; no runtime allocation) ------------
__device__ float g_xg[TSEQ * GC * BATCH];            // 256 MB, [t][col][b]
__device__ float g_hist[TSEQ * 512 * BATCH];         // h history fp32 [t][dir*256+u][b]
__device__ __nv_bfloat16 g_hbf[TSEQ * 2 * 2 * 256 * 32];  // [t][dir][hi/lo][u][b]
__device__ unsigned int g_cnt[64];                   // per-direction barrier counters

// ---- PTX helpers -------------------------------------------------------------
#define CP_ASYNC16(dst_u32, src_ptr) \
    asm volatile("cp.async.cg.shared.global [%0], [%1], 16;" :: "r"(dst_u32), "l"(src_ptr))
#define CP_COMMIT() asm volatile("cp.async.commit_group;" ::: "memory")
#define CP_WAIT(n)  asm volatile("cp.async.wait_group %0;" :: "n"(n) : "memory")

__device__ __forceinline__ unsigned smem_u32(const void* p) {
    unsigned a;
    asm("{ .reg .u64 t; cvta.to.shared.u64 t, %1; cvt.u32.u64 %0, t; }" : "=r"(a) : "l"(p));
    return a;
}
__device__ __forceinline__ float fast_tanh(float x) {
    float r;
    asm("tanh.approx.f32 %0, %1;" : "=f"(r) : "f"(x));
    return r;
}

#define LDSM_X4(r, addr) \
    asm volatile("ldmatrix.sync.aligned.m8n8.x4.shared.b16 {%0,%1,%2,%3}, [%4];" \
                 : "=r"((r)[0]), "=r"((r)[1]), "=r"((r)[2]), "=r"((r)[3]) : "r"(addr))
#define LDSM_X4T(r, addr) \
    asm volatile("ldmatrix.sync.aligned.m8n8.x4.trans.shared.b16 {%0,%1,%2,%3}, [%4];" \
                 : "=r"((r)[0]), "=r"((r)[1]), "=r"((r)[2]), "=r"((r)[3]) : "r"(addr))
#define LDSM_X2(r, addr) \
    asm volatile("ldmatrix.sync.aligned.m8n8.x2.shared.b16 {%0,%1}, [%2];" \
                 : "=r"((r)[0]), "=r"((r)[1]) : "r"(addr))

#define MMA_BF16(d, a, b0, b1) \
    asm volatile("mma.sync.aligned.m16n8k16.row.col.f32.bf16.bf16.f32 " \
                 "{%0,%1,%2,%3}, {%4,%5,%6,%7}, {%8,%9}, {%0,%1,%2,%3};" \
                 : "+f"((d)[0]), "+f"((d)[1]), "+f"((d)[2]), "+f"((d)[3]) \
                 : "r"((a)[0]), "r"((a)[1]), "r"((a)[2]), "r"((a)[3]), \
                   "r"(b0), "r"(b1))

// split fp32 pair -> (hi, lo) bf16x2
__device__ __forceinline__ void cvt_split2(float2 f, uint32_t& h, uint32_t& l) {
    __nv_bfloat162 h2 = __float22bfloat162_rn(f);
    float2 hf = __bfloat1622float2(h2);
    __nv_bfloat162 l2 = __float22bfloat162_rn(make_float2(f.x - hf.x, f.y - hf.y));
    h = *(uint32_t*)&h2;
    l = *(uint32_t*)&l2;
}

// ---------------- tensor-core input projection: xg = x @ kernel --------------
// (unchanged from R9/R10 best: ~683us)
#define LDA 40

__global__ void __launch_bounds__(256, 2) gemm_mma(const float* __restrict__ x,
                                                   const float* __restrict__ Wk) {
    __shared__ __align__(16) __nv_bfloat16 Ah[128 * LDA];
    __shared__ __align__(16) __nv_bfloat16 Al[128 * LDA];
    __shared__ __align__(16) __nv_bfloat16 Bh[128 * LDA];
    __shared__ __align__(16) __nv_bfloat16 Bl[128 * LDA];

    const int tid = threadIdx.x;
    if (blockIdx.x == 0 && blockIdx.y == 0 && tid < 64) g_cnt[tid] = 0u;

    const int w    = tid >> 5;
    const int lane = tid & 31;
    const int warp_m = (w & 3) * 32;
    const int warp_n = (w >> 2) * 64;
    const int n0 = blockIdx.x * 128;
    const int t0 = blockIdx.y * 4;

    const uint32_t ah_s = smem_u32(Ah), al_s = smem_u32(Al);
    const uint32_t bh_s = smem_u32(Bh), bl_s = smem_u32(Bl);

    float acc[2][8][4];
#pragma unroll
    for (int mt = 0; mt < 2; mt++)
#pragma unroll
        for (int nf = 0; nf < 8; nf++)
#pragma unroll
            for (int q = 0; q < 4; q++) acc[mt][nf][q] = 0.f;

    const int a_r  = lane & 15;
    const int a_c8 = (lane >> 4) * 8;
    const int b_nr = (lane & 7) + ((lane >> 4) & 1) * 8;
    const int b_k8 = ((lane >> 3) & 1) * 8;

    for (int kc = 0; kc < DIN; kc += 32) {
#pragma unroll
        for (int i = 0; i < 4; i++) {
            int idx = tid + i * 256;
            int mloc = idx >> 3, q = idx & 7;
            const float* src = &x[((size_t)(mloc & 31) * TSEQ + t0 + (mloc >> 5)) * DIN + kc + q * 4];
            float4 v = *(const float4*)src;
            uint32_t h01, l01, h23, l23;
            cvt_split2(make_float2(v.x, v.y), h01, l01);
            cvt_split2(make_float2(v.z, v.w), h23, l23);
            int o = mloc * LDA + q * 4;
            *(uint32_t*)&Ah[o] = h01; *(uint32_t*)&Ah[o + 2] = h23;
            *(uint32_t*)&Al[o] = l01; *(uint32_t*)&Al[o + 2] = l23;
        }
#pragma unroll
        for (int i = 0; i < 4; i++) {
            int idx = tid + i * 256;
            int kk = idx >> 5, nq = idx & 31;
            const float* src = &Wk[(size_t)(kc + kk) * GC + n0 + nq * 4];
            float4 v = *(const float4*)src;
            float f[4] = {v.x, v.y, v.z, v.w};
#pragma unroll
            for (int j = 0; j < 4; j++) {
                __nv_bfloat16 hb = __float2bfloat16_rn(f[j]);
                __nv_bfloat16 lb = __float2bfloat16_rn(f[j] - __bfloat162float(hb));
                int o = (nq * 4 + j) * LDA + kk;
                Bh[o] = hb;
                Bl[o] = lb;
            }
        }
        __syncthreads();

#pragma unroll
        for (int ks = 0; ks < 2; ks++) {
            const int k0 = ks * 16;
            uint32_t afh[2][4], afl[2][4];
#pragma unroll
            for (int mt = 0; mt < 2; mt++) {
                uint32_t off = (uint32_t)((warp_m + mt * 16 + a_r) * LDA + k0 + a_c8) * 2u;
                LDSM_X4(afh[mt], ah_s + off);
                LDSM_X4(afl[mt], al_s + off);
            }
            uint32_t bfr[4][4];
#pragma unroll
            for (int bt = 0; bt < 4; bt++) {
                uint32_t off = (uint32_t)((warp_n + bt * 16 + b_nr) * LDA + k0 + b_k8) * 2u;
                LDSM_X4(bfr[bt], bh_s + off);
            }
#pragma unroll
            for (int mt = 0; mt < 2; mt++)
#pragma unroll
                for (int bt = 0; bt < 4; bt++) {
                    MMA_BF16(acc[mt][bt * 2],     afh[mt], bfr[bt][0], bfr[bt][1]);
                    MMA_BF16(acc[mt][bt * 2 + 1], afh[mt], bfr[bt][2], bfr[bt][3]);
                    MMA_BF16(acc[mt][bt * 2],     afl[mt], bfr[bt][0], bfr[bt][1]);
                    MMA_BF16(acc[mt][bt * 2 + 1], afl[mt], bfr[bt][2], bfr[bt][3]);
                }
#pragma unroll
            for (int bt = 0; bt < 4; bt++) {
                uint32_t off = (uint32_t)((warp_n + bt * 16 + b_nr) * LDA + k0 + b_k8) * 2u;
                LDSM_X4(bfr[bt], bl_s + off);
            }
#pragma unroll
            for (int mt = 0; mt < 2; mt++)
#pragma unroll
                for (int bt = 0; bt < 4; bt++) {
                    MMA_BF16(acc[mt][bt * 2],     afh[mt], bfr[bt][0], bfr[bt][1]);
                    MMA_BF16(acc[mt][bt * 2 + 1], afh[mt], bfr[bt][2], bfr[bt][3]);
                }
        }
        __syncthreads();
    }

#pragma unroll
    for (int mt = 0; mt < 2; mt++) {
        int m0 = warp_m + mt * 16 + (lane >> 2);
        int m1 = m0 + 8;
        int ta = t0 + (m0 >> 5), ba = m0 & 31;
        int tb = t0 + (m1 >> 5), bb = m1 & 31;
#pragma unroll
        for (int nf = 0; nf < 8; nf++) {
            int n = n0 + warp_n + nf * 8 + (lane & 3) * 2;
            float* pa = &g_xg[((size_t)ta * GC + n) * BATCH + ba];
            float* pb = &g_xg[((size_t)tb * GC + n) * BATCH + bb];
            pa[0]     = acc[mt][nf][0];
            pa[BATCH] = acc[mt][nf][1];
            pb[0]     = acc[mt][nf][2];
            pb[BATCH] = acc[mt][nf][3];
        }
    }
}

// ---------------- persistent recurrent scan: HMMA dot, 16 CTAs/dir -----------
// 32 CTAs (16/dir), 256 threads. CTA owns 16 units (64 gate cols).
// warp w: kh = w>>2 (k-half), nh = w&3 (16-col group). Per warp per step:
// batch32 x col16 x k128 bf16 3-term = 96 MMA + 32 LDSM. W fragments preloaded
// in registers (two-pass prestage). Gs partials alias the hs staging buffer.
// Barrier mechanism = R5 exactly; only the participant count shrinks (64->16).
__global__ void __launch_bounds__(256, 1) blstm_rec(const float* __restrict__ rk) {
    __shared__ __align__(16) char hs_area[2 * 256 * LDH];   // 40960 B
    float* Gs = (float*)hs_area;   // [2][64][33] = 16896 B, live dot-end..epilogue

    const int tid  = threadIdx.x;
    const int lane = tid & 31;
    const int w    = tid >> 5;
    const int kh   = w >> 2;
    const int nh   = w & 3;
    const int gtid = tid & 127;
    const int dir  = blockIdx.x >> 4;
    const int cta  = blockIdx.x & 15;
    const int u0   = cta * 16;

    // ---- one-time: preload W^T fragments (hi, lo) via two passes through smem
    uint32_t bfh[8][2][2], bfl[8][2][2];
    {
        __nv_bfloat16* Wsm = (__nv_bfloat16*)hs_area;   // [64 n][264 k]
        const uint32_t wb = smem_u32(hs_area);
        const int ln = lane & 15;
        // pass 1: hi
        for (int i = tid; i < 64 * 256; i += 256) {
            int n = i >> 8, k = i & 255;
            float v = rk[(size_t)k * GC + dir * G4 + (n & 3) * 256 + u0 + (n >> 2)];
            Wsm[n * 264 + k] = __float2bfloat16_rn(v);
        }
        __syncthreads();
#pragma unroll
        for (int nt = 0; nt < 2; nt++) {
            uint32_t loff = (uint32_t)(nh * 16 + nt * 8 + (ln & 7)) * 528u
                          + ((ln >> 3) ? 16u : 0u) + (uint32_t)kh * 256u;
#pragma unroll
            for (int ks = 0; ks < 8; ks++) LDSM_X2(bfh[ks][nt], wb + loff + ks * 32u);
        }
        __syncthreads();
        // pass 2: lo
        for (int i = tid; i < 64 * 256; i += 256) {
            int n = i >> 8, k = i & 255;
            float v = rk[(size_t)k * GC + dir * G4 + (n & 3) * 256 + u0 + (n >> 2)];
            __nv_bfloat16 hb = __float2bfloat16_rn(v);
            Wsm[n * 264 + k] = __float2bfloat16_rn(v - __bfloat162float(hb));
        }
        __syncthreads();
#pragma unroll
        for (int nt = 0; nt < 2; nt++) {
            uint32_t loff = (uint32_t)(nh * 16 + nt * 8 + (ln & 7)) * 528u
                          + ((ln >> 3) ? 16u : 0u) + (uint32_t)kh * 256u;
#pragma unroll
            for (int ks = 0; ks < 8; ks++) LDSM_X2(bfl[ks][nt], wb + loff + ks * 32u);
        }
        __syncthreads();
    }

    // ---- A-fragment ldmatrix lane offsets (constant per step)
    const uint32_t hsH = smem_u32(hs_area);
    const uint32_t hsL = hsH + 256 * LDH;
    uint32_t a_loff[2];
    {
        int q = lane >> 3, i = lane & 7;
        int row = kh * 128 + (q >> 1) * 8 + i;
#pragma unroll
        for (int mt = 0; mt < 2; mt++)
            a_loff[mt] = (uint32_t)row * LDH + (uint32_t)((mt * 16 + (q & 1) * 8) * 2);
    }

    unsigned int* cnt = &g_cnt[dir * 32];
    float c_state[2] = {0.f, 0.f};
    int tprev = 0;

    for (int s = 0; s < TSEQ; s++) {
        const int t = dir ? (TSEQ - 1 - s) : s;

        // gate-bias DRAM loads: every thread owns units (w*2, w*2+1), lane=b
        float bias[2][4];
        {
            const float* xgp = &g_xg[((size_t)t * GC + dir * G4) * BATCH];
#pragma unroll
            for (int j = 0; j < 2; j++) {
                int uu = u0 + w * 2 + j;
#pragma unroll
                for (int g = 0; g < 4; g++)
                    bias[j][g] = __ldcs(&xgp[((size_t)g * UNITS + uu) * BATCH + lane]);
            }
        }

        float acc[2][2][4];
#pragma unroll
        for (int mt = 0; mt < 2; mt++)
#pragma unroll
            for (int nt = 0; nt < 2; nt++)
#pragma unroll
                for (int q = 0; q < 4; q++) acc[mt][nt][q] = 0.f;

        if (s > 0) {
            // stage this k-half of h (hi+lo): 8KB+8KB per kh-group
            const char* srcH = (const char*)g_hbf
                + (((size_t)tprev * 2 + dir) * 2 + 0) * 16384 + (size_t)kh * 8192;
            const char* srcL = srcH + 16384;
            const uint32_t dstH = hsH + (uint32_t)kh * 128u * LDH;
            const uint32_t dstL = hsL + (uint32_t)kh * 128u * LDH;
#pragma unroll
            for (int j = 0; j < 4; j++) {
                int c = gtid + j * 128;
                int row = c >> 2, ch = c & 3;
                CP_ASYNC16(dstH + (uint32_t)row * LDH + ch * 16u, srcH + row * 64 + ch * 16);
            }
#pragma unroll
            for (int j = 0; j < 4; j++) {
                int c = gtid + j * 128;
                int row = c >> 2, ch = c & 3;
                CP_ASYNC16(dstL + (uint32_t)row * LDH + ch * 16u, srcL + row * 64 + ch * 16);
            }
            CP_COMMIT();
            CP_WAIT(0);
            asm volatile("bar.sync %0, 128;" :: "r"(1 + kh) : "memory");

            // 8 ksteps: 4 ldmatrix.trans + 12 MMA each
#pragma unroll
            for (int ks = 0; ks < 8; ks++) {
                uint32_t ah[2][4], al[2][4];
#pragma unroll
                for (int mt = 0; mt < 2; mt++) {
                    LDSM_X4T(ah[mt], hsH + a_loff[mt] + ks * (16u * LDH));
                    LDSM_X4T(al[mt], hsL + a_loff[mt] + ks * (16u * LDH));
                }
#pragma unroll
                for (int mt = 0; mt < 2; mt++)
#pragma unroll
                    for (int nt = 0; nt < 2; nt++) {
                        MMA_BF16(acc[mt][nt], ah[mt], bfh[ks][nt][0], bfh[ks][nt][1]);
                        MMA_BF16(acc[mt][nt], al[mt], bfh[ks][nt][0], bfh[ks][nt][1]);
                        MMA_BF16(acc[mt][nt], ah[mt], bfl[ks][nt][0], bfl[ks][nt][1]);
                    }
            }
        }
        __syncthreads();    // all hs reads done; Gs may alias

        // write partials: Gs[kh][n][m]
#pragma unroll
        for (int mt = 0; mt < 2; mt++)
#pragma unroll
            for (int nt = 0; nt < 2; nt++) {
                int m0 = mt * 16 + (lane >> 2);
                int n0 = nh * 16 + nt * 8 + (lane & 3) * 2;
                Gs[(kh * 64 + n0) * 33 + m0]           = acc[mt][nt][0];
                Gs[(kh * 64 + n0 + 1) * 33 + m0]       = acc[mt][nt][1];
                Gs[(kh * 64 + n0) * 33 + m0 + 8]       = acc[mt][nt][2];
                Gs[(kh * 64 + n0 + 1) * 33 + m0 + 8]   = acc[mt][nt][3];
            }
        __syncthreads();

        // epilogue: all 8 warps, 2 units per thread
#pragma unroll
        for (int j = 0; j < 2; j++) {
            const int cu = w * 2 + j;
            float ai = Gs[(cu * 4 + 0) * 33 + lane] + Gs[(64 + cu * 4 + 0) * 33 + lane] + bias[j][0];
            float af = Gs[(cu * 4 + 1) * 33 + lane] + Gs[(64 + cu * 4 + 1) * 33 + lane] + bias[j][1];
            float am = Gs[(cu * 4 + 2) * 33 + lane] + Gs[(64 + cu * 4 + 2) * 33 + lane] + bias[j][2];
            float ao = Gs[(cu * 4 + 3) * 33 + lane] + Gs[(64 + cu * 4 + 3) * 33 + lane] + bias[j][3];

            float gi = __saturatef(0.2f * ai + 0.5f);
            float gf = __saturatef(0.2f * af + 0.5f);
            float gm = fast_tanh(am);
            float go = __saturatef(0.2f * ao + 0.5f);
            c_state[j] = gf * c_state[j] + gi * gm;
            float h = go * fast_tanh(c_state[j]);

            const int u = u0 + cu;
            g_hist[((size_t)t * 512 + dir * 256 + u) * BATCH + lane] = h;
            __nv_bfloat16 hh = __float2bfloat16_rn(h);
            __nv_bfloat16 hl = __float2bfloat16_rn(h - __bfloat162float(hh));
            size_t hb = (((size_t)t * 2 + dir) * 2) * 8192 + (size_t)u * 32 + lane;
            g_hbf[hb]        = hh;
            g_hbf[hb + 8192] = hl;
        }

        // ---- per-direction grid barrier (R5 mechanism; 16 participants)
        __syncthreads();
        if (tid == 0) {
            asm volatile("red.release.gpu.global.add.u32 [%0], 1;" :: "l"(cnt) : "memory");
            const unsigned target = (unsigned)(s + 1) * 16u;
            unsigned v;
            asm volatile("ld.acquire.gpu.global.u32 %0, [%1];" : "=r"(v) : "l"(cnt) : "memory");
            while (v < target) {
                __nanosleep(32);
                asm volatile("ld.acquire.gpu.global.u32 %0, [%1];" : "=r"(v) : "l"(cnt) : "memory");
            }
        }
        __syncthreads();
        tprev = t;
    }
}

// ---------------- final transpose: out[b][t][c] = hist[t][c][b] --------------
__global__ void __launch_bounds__(256) transpose_out(float* __restrict__ out) {
    __shared__ float S[128 * 33];
    const int t  = blockIdx.x;
    const int c0 = blockIdx.y * 128;
    const int tid = threadIdx.x;

    const float* src = &g_hist[((size_t)t * 512 + c0) * BATCH];
#pragma unroll
    for (int i = 0; i < 4; i++) {
        int idx4 = tid + i * 256;
        float4 v = ((const float4*)src)[idx4];
        int e = idx4 * 4;
        int c = e >> 5, b0 = e & 31;
        float* d = &S[c * 33 + b0];
        d[0] = v.x; d[1] = v.y; d[2] = v.z; d[3] = v.w;
    }
    __syncthreads();

    const int lane = tid & 31;
    const int bq   = tid >> 5;
#pragma unroll
    for (int i = 0; i < 4; i++) {
        int b = bq + i * 8;
        int cc = lane * 4;
        float4 v = make_float4(S[(cc + 0) * 33 + b], S[(cc + 1) * 33 + b],
                               S[(cc + 2) * 33 + b], S[(cc + 3) * 33 + b]);
        *(float4*)&out[((size_t)b * TSEQ + t) * 512 + c0 + cc] = v;
    }
}

// ---------------- entry ------------------------------------------------------
extern "C" void kernel_launch(void* const* d_in, const int* in_sizes, int n_in,
                              void* d_out, int out_size) {
    (void)in_sizes; (void)n_in; (void)out_size;
    const float* x    = (const float*)d_in[0];   // [32,1024,256]
    const float* kern = (const float*)d_in[1];   // [256,2048]
    const float* rk   = (const float*)d_in[2];   // [256,2048]
    float* out = (float*)d_out;                  // [32,1024,512]

    dim3 ggrid(GC / 128, (BATCH * TSEQ) / 128);  // (16, 256)
    gemm_mma<<<ggrid, 256>>>(x, kern);
    blstm_rec<<<32, 256>>>(rk);
    dim3 tgrid(TSEQ, 4);
    transpose_out<<<tgrid, 256>>>(out);
}

// round 14
// speedup vs baseline: 1.2924x; 1.2924x over previous
#include <cuda_runtime.h>
#include <cuda_bf16.h>
#include <cstdint>

#define BATCH 32
#define TSEQ  1024
#define DIN   256
#define UNITS 256
#define GC    2048   // 8*U total gate columns
#define G4    1024   // 4*U per direction
#define LDH   80     // padded hs row stride in bytes (32 bf16 = 64B data + 16B pad)

// ---------------- scratch (device globals; no runtime allocation) ------------
__device__ float g_xg[TSEQ * GC * BATCH];            // 256 MB, [t][col][b]
__device__ __nv_bfloat16 g_hbf[TSEQ * 2 * 2 * 256 * 32];  // [t][dir][hi/lo][u][b]
__device__ unsigned int g_cnt[64];                   // per-direction barrier counters
// pre-converted bf16 (hi, lo) operands for the input GEMM
__device__ __nv_bfloat16 g_xh[TSEQ * BATCH * DIN];   // [m = t*32+b][k]
__device__ __nv_bfloat16 g_xl[TSEQ * BATCH * DIN];
__device__ __nv_bfloat16 g_wh[GC * DIN];             // [n][k]
__device__ __nv_bfloat16 g_wl[GC * DIN];

// ---- PTX helpers -------------------------------------------------------------
#define CP_ASYNC16(dst_u32, src_ptr) \
    asm volatile("cp.async.cg.shared.global [%0], [%1], 16;" :: "r"(dst_u32), "l"(src_ptr))
#define CP_COMMIT() asm volatile("cp.async.commit_group;" ::: "memory")
#define CP_WAIT(n)  asm volatile("cp.async.wait_group %0;" :: "n"(n) : "memory")

__device__ __forceinline__ unsigned smem_u32(const void* p) {
    unsigned a;
    asm("{ .reg .u64 t; cvta.to.shared.u64 t, %1; cvt.u32.u64 %0, t; }" : "=r"(a) : "l"(p));
    return a;
}
__device__ __forceinline__ float fast_tanh(float x) {
    float r;
    asm("tanh.approx.f32 %0, %1;" : "=f"(r) : "f"(x));
    return r;
}

#define LDSM_X4(r, addr) \
    asm volatile("ldmatrix.sync.aligned.m8n8.x4.shared.b16 {%0,%1,%2,%3}, [%4];" \
                 : "=r"((r)[0]), "=r"((r)[1]), "=r"((r)[2]), "=r"((r)[3]) : "r"(addr))
#define LDSM_X4T(r, addr) \
    asm volatile("ldmatrix.sync.aligned.m8n8.x4.trans.shared.b16 {%0,%1,%2,%3}, [%4];" \
                 : "=r"((r)[0]), "=r"((r)[1]), "=r"((r)[2]), "=r"((r)[3]) : "r"(addr))
#define LDSM_X2(r, addr) \
    asm volatile("ldmatrix.sync.aligned.m8n8.x2.shared.b16 {%0,%1}, [%2];" \
                 : "=r"((r)[0]), "=r"((r)[1]) : "r"(addr))

#define MMA_BF16(d, a, b0, b1) \
    asm volatile("mma.sync.aligned.m16n8k16.row.col.f32.bf16.bf16.f32 " \
                 "{%0,%1,%2,%3}, {%4,%5,%6,%7}, {%8,%9}, {%0,%1,%2,%3};" \
                 : "+f"((d)[0]), "+f"((d)[1]), "+f"((d)[2]), "+f"((d)[3]) \
                 : "r"((a)[0]), "r"((a)[1]), "r"((a)[2]), "r"((a)[3]), \
                   "r"(b0), "r"(b1))

// split fp32 pair -> (hi, lo) bf16x2
__device__ __forceinline__ void cvt_split2(float2 f, uint32_t& h, uint32_t& l) {
    __nv_bfloat162 h2 = __float22bfloat162_rn(f);
    float2 hf = __bfloat1622float2(h2);
    __nv_bfloat162 l2 = __float22bfloat162_rn(make_float2(f.x - hf.x, f.y - hf.y));
    h = *(uint32_t*)&h2;
    l = *(uint32_t*)&l2;
}

// ---------------- pre-conversion: x -> (g_xh, g_xl) [m][k] -------------------
// grid (TSEQ/4, BATCH), 256 threads. Coalesced read + coalesced write.
__global__ void __launch_bounds__(256) prep_x(const float* __restrict__ x) {
    const int tid = threadIdx.x;
    const int t = blockIdx.x * 4 + (tid >> 6);
    const int b = blockIdx.y;
    const int k4 = (tid & 63) * 4;
    float4 v = *(const float4*)&x[((size_t)b * TSEQ + t) * DIN + k4];
    uint32_t h01, l01, h23, l23;
    cvt_split2(make_float2(v.x, v.y), h01, l01);
    cvt_split2(make_float2(v.z, v.w), h23, l23);
    size_t o = ((size_t)t * 32 + b) * DIN + k4;
    *(uint32_t*)&g_xh[o] = h01; *(uint32_t*)&g_xh[o + 2] = h23;
    *(uint32_t*)&g_xl[o] = l01; *(uint32_t*)&g_xl[o + 2] = l23;
}

// ---------------- pre-conversion: W -> (g_wh, g_wl) [n][k] transposed --------
// grid (GC/32, DIN/32), 256 threads; 32x32 smem tile transpose.
__global__ void __launch_bounds__(256) prep_w(const float* __restrict__ Wk) {
    __shared__ float S[32][33];
    const int n0 = blockIdx.x * 32, k0 = blockIdx.y * 32;
    const int tid = threadIdx.x;
#pragma unroll
    for (int i = 0; i < 4; i++) {
        int e = tid + i * 256;
        int kk = e >> 5, nn = e & 31;
        S[kk][nn] = Wk[(size_t)(k0 + kk) * GC + n0 + nn];
    }
    __syncthreads();
#pragma unroll
    for (int i = 0; i < 4; i++) {
        int e = tid + i * 256;
        int nn = e >> 5, kk = e & 31;
        float v = S[kk][nn];
        __nv_bfloat16 hb = __float2bfloat16_rn(v);
        g_wh[(size_t)(n0 + nn) * DIN + k0 + kk] = hb;
        g_wl[(size_t)(n0 + nn) * DIN + k0 + kk] = __float2bfloat16_rn(v - __bfloat162float(hb));
    }
}

// ---------------- tensor-core input projection: xg = x @ kernel --------------
// M = 32768 (m = t*32 + b), N = 2048, K = 256. CTA tile 128Mx128N, 8 warps,
// warp tile 32Mx64N, K in 8 chunks of 32. Operands pre-converted to bf16
// (hi,lo) in global; staging is pure 16B cp.async, zero in-loop conversion.
#define LDA 40

__global__ void __launch_bounds__(256, 2) gemm_mma(const float* __restrict__ dummy0,
                                                   const float* __restrict__ dummy1) {
    __shared__ __align__(16) __nv_bfloat16 Ah[128 * LDA];
    __shared__ __align__(16) __nv_bfloat16 Al[128 * LDA];
    __shared__ __align__(16) __nv_bfloat16 Bh[128 * LDA];
    __shared__ __align__(16) __nv_bfloat16 Bl[128 * LDA];

    const int tid = threadIdx.x;
    if (blockIdx.x == 0 && blockIdx.y == 0 && tid < 64) g_cnt[tid] = 0u;

    const int w    = tid >> 5;
    const int lane = tid & 31;
    const int warp_m = (w & 3) * 32;
    const int warp_n = (w >> 2) * 64;
    const int n0 = blockIdx.x * 128;
    const int t0 = blockIdx.y * 4;
    const int m0g = t0 * 32;                // global m row of tile row 0

    const uint32_t ah_s = smem_u32(Ah), al_s = smem_u32(Al);
    const uint32_t bh_s = smem_u32(Bh), bl_s = smem_u32(Bl);

    float acc[2][8][4];
#pragma unroll
    for (int mt = 0; mt < 2; mt++)
#pragma unroll
        for (int nf = 0; nf < 8; nf++)
#pragma unroll
            for (int q = 0; q < 4; q++) acc[mt][nf][q] = 0.f;

    const int a_r  = lane & 15;
    const int a_c8 = (lane >> 4) * 8;
    const int b_nr = (lane & 7) + ((lane >> 4) & 1) * 8;
    const int b_k8 = ((lane >> 3) & 1) * 8;

    for (int kc = 0; kc < DIN; kc += 32) {
        // ---- stage all 4 matrices via cp.async: 512 x 16B chunks each
#pragma unroll
        for (int i = 0; i < 2; i++) {
            int c = tid + i * 256;           // 0..511
            int row = c >> 2, q = c & 3;
            uint32_t doff = (uint32_t)row * 80u + (uint32_t)q * 16u;
            size_t aoff = ((size_t)(m0g + row)) * DIN + kc + q * 8;
            size_t boff = ((size_t)(n0 + row)) * DIN + kc + q * 8;
            CP_ASYNC16(ah_s + doff, g_xh + aoff);
            CP_ASYNC16(al_s + doff, g_xl + aoff);
            CP_ASYNC16(bh_s + doff, g_wh + boff);
            CP_ASYNC16(bl_s + doff, g_wl + boff);
        }
        CP_COMMIT();
        CP_WAIT(0);
        __syncthreads();

#pragma unroll
        for (int ks = 0; ks < 2; ks++) {
            const int k0 = ks * 16;
            uint32_t afh[2][4], afl[2][4];
#pragma unroll
            for (int mt = 0; mt < 2; mt++) {
                uint32_t off = (uint32_t)((warp_m + mt * 16 + a_r) * LDA + k0 + a_c8) * 2u;
                LDSM_X4(afh[mt], ah_s + off);
                LDSM_X4(afl[mt], al_s + off);
            }
            uint32_t bfr[4][4];
#pragma unroll
            for (int bt = 0; bt < 4; bt++) {
                uint32_t off = (uint32_t)((warp_n + bt * 16 + b_nr) * LDA + k0 + b_k8) * 2u;
                LDSM_X4(bfr[bt], bh_s + off);
            }
#pragma unroll
            for (int mt = 0; mt < 2; mt++)
#pragma unroll
                for (int bt = 0; bt < 4; bt++) {
                    MMA_BF16(acc[mt][bt * 2],     afh[mt], bfr[bt][0], bfr[bt][1]);
                    MMA_BF16(acc[mt][bt * 2 + 1], afh[mt], bfr[bt][2], bfr[bt][3]);
                    MMA_BF16(acc[mt][bt * 2],     afl[mt], bfr[bt][0], bfr[bt][1]);
                    MMA_BF16(acc[mt][bt * 2 + 1], afl[mt], bfr[bt][2], bfr[bt][3]);
                }
#pragma unroll
            for (int bt = 0; bt < 4; bt++) {
                uint32_t off = (uint32_t)((warp_n + bt * 16 + b_nr) * LDA + k0 + b_k8) * 2u;
                LDSM_X4(bfr[bt], bl_s + off);
            }
#pragma unroll
            for (int mt = 0; mt < 2; mt++)
#pragma unroll
                for (int bt = 0; bt < 4; bt++) {
                    MMA_BF16(acc[mt][bt * 2],     afh[mt], bfr[bt][0], bfr[bt][1]);
                    MMA_BF16(acc[mt][bt * 2 + 1], afh[mt], bfr[bt][2], bfr[bt][3]);
                }
        }
        __syncthreads();
    }

#pragma unroll
    for (int mt = 0; mt < 2; mt++) {
        int m0 = warp_m + mt * 16 + (lane >> 2);
        int m1 = m0 + 8;
        int ta = t0 + (m0 >> 5), ba = m0 & 31;
        int tb = t0 + (m1 >> 5), bb = m1 & 31;
#pragma unroll
        for (int nf = 0; nf < 8; nf++) {
            int n = n0 + warp_n + nf * 8 + (lane & 3) * 2;
            float* pa = &g_xg[((size_t)ta * GC + n) * BATCH + ba];
            float* pb = &g_xg[((size_t)tb * GC + n) * BATCH + bb];
            pa[0]     = acc[mt][nf][0];
            pa[BATCH] = acc[mt][nf][1];
            pb[0]     = acc[mt][nf][2];
            pb[BATCH] = acc[mt][nf][3];
        }
    }
}

// ---------------- persistent recurrent scan: HMMA dot (R10 best, verbatim) ---
// 128 CTAs (64/dir), 256 threads. CTA owns 4 units (16 gate cols).
// warp w: kh = w>>2, mh = (w>>1)&1, nh = w&1. W fragments preloaded in regs;
// h staged as bf16 (hi,lo) from g_hbf via cp.async + ldmatrix.x4.trans.
// Barrier = R5 single counter + red.release + backoff poll. DO NOT REDESIGN.
__global__ void __launch_bounds__(256, 1) blstm_rec(const float* __restrict__ rk) {
    __shared__ __align__(16) char hs_area[2 * 256 * LDH];   // 40960 B
    __shared__ float Gs[2][16][33];                         // per-k-half gate partials

    const int tid  = threadIdx.x;
    const int lane = tid & 31;
    const int w    = tid >> 5;
    const int kh   = w >> 2;
    const int mh   = (w >> 1) & 1;
    const int nh   = w & 1;
    const int gtid = tid & 127;
    const int dir  = blockIdx.x >> 6;
    const int cta  = blockIdx.x & 63;
    const int u0   = cta * 4;

    // ---- one-time: build W^T (hi,lo) bf16 in smem, padded rows of 264 halves
    {
        __nv_bfloat16* Wh_sm = (__nv_bfloat16*)hs_area;
        __nv_bfloat16* Wl_sm = (__nv_bfloat16*)(hs_area + 8448);
        for (int i = tid; i < 16 * 256; i += 256) {
            int n = i >> 8, k = i & 255;
            float v = rk[(size_t)k * GC + dir * G4 + (n & 3) * 256 + u0 + (n >> 2)];
            __nv_bfloat16 hb = __float2bfloat16_rn(v);
            Wh_sm[n * 264 + k] = hb;
            Wl_sm[n * 264 + k] = __float2bfloat16_rn(v - __bfloat162float(hb));
        }
    }
    __syncthreads();

    // ---- preload B fragments (per warp: 8 ksteps x {hi,lo} x 2 regs)
    uint32_t bfh[8][2], bfl[8][2];
    {
        const uint32_t whb = smem_u32(hs_area);
        const uint32_t wlb = whb + 8448;
        int ln = lane & 15;
        uint32_t loff = (uint32_t)(nh * 8 + (ln & 7)) * 528u + ((ln >> 3) ? 16u : 0u)
                        + (uint32_t)kh * 256u;
#pragma unroll
        for (int ks = 0; ks < 8; ks++) {
            LDSM_X2(bfh[ks], whb + loff + ks * 32u);
            LDSM_X2(bfl[ks], wlb + loff + ks * 32u);
        }
    }
    __syncthreads();   // done reading W^T; hs_area free for staging

    // ---- A-fragment ldmatrix lane offsets (constant per step)
    const uint32_t hsH = smem_u32(hs_area);
    const uint32_t hsL = hsH + 256 * LDH;
    uint32_t a_loff;
    {
        int q = lane >> 3, i = lane & 7;
        int row = kh * 128 + (q >> 1) * 8 + i;
        int colb = (mh * 16 + (q & 1) * 8) * 2;
        a_loff = (uint32_t)row * LDH + (uint32_t)colb;
    }

    unsigned int* cnt = &g_cnt[dir * 32];
    float c_state = 0.f;
    int tprev = 0;

    for (int s = 0; s < TSEQ; s++) {
        const int t = dir ? (TSEQ - 1 - s) : s;

        // gate-bias DRAM loads (kh=0 warps: thread (wu=w, lane=b))
        float bi, bf_, bm, bo;
        if (kh == 0) {
            const float* xgp = &g_xg[((size_t)t * GC + dir * G4) * BATCH];
            bi  = __ldcs(&xgp[(0 * UNITS + u0 + w) * BATCH + lane]);
            bf_ = __ldcs(&xgp[(1 * UNITS + u0 + w) * BATCH + lane]);
            bm  = __ldcs(&xgp[(2 * UNITS + u0 + w) * BATCH + lane]);
            bo  = __ldcs(&xgp[(3 * UNITS + u0 + w) * BATCH + lane]);
        }

        float acc[4] = {0.f, 0.f, 0.f, 0.f};

        if (s > 0) {
            // stage this k-half of h (hi+lo) from g_hbf: 8KB per matrix per group
            const char* srcH = (const char*)g_hbf
                + (((size_t)tprev * 2 + dir) * 2 + 0) * 16384 + (size_t)kh * 8192;
            const char* srcL = srcH + 16384;
            const uint32_t dstH = hsH + (uint32_t)kh * 128u * LDH;
            const uint32_t dstL = hsL + (uint32_t)kh * 128u * LDH;
#pragma unroll
            for (int j = 0; j < 4; j++) {
                int c = gtid + j * 128;
                int row = c >> 2, ch = c & 3;
                CP_ASYNC16(dstH + (uint32_t)row * LDH + ch * 16u, srcH + row * 64 + ch * 16);
            }
#pragma unroll
            for (int j = 0; j < 4; j++) {
                int c = gtid + j * 128;
                int row = c >> 2, ch = c & 3;
                CP_ASYNC16(dstL + (uint32_t)row * LDH + ch * 16u, srcL + row * 64 + ch * 16);
            }
            CP_COMMIT();
            CP_WAIT(0);
            asm volatile("bar.sync %0, 128;" :: "r"(1 + kh) : "memory");

            // 8 ksteps: 2 ldmatrix.trans + 3 MMA each
#pragma unroll
            for (int ks = 0; ks < 8; ks++) {
                uint32_t ah[4], al[4];
                LDSM_X4T(ah, hsH + a_loff + ks * (16u * LDH));
                LDSM_X4T(al, hsL + a_loff + ks * (16u * LDH));
                MMA_BF16(acc, ah, bfh[ks][0], bfh[ks][1]);
                MMA_BF16(acc, al, bfh[ks][0], bfh[ks][1]);
                MMA_BF16(acc, ah, bfl[ks][0], bfl[ks][1]);
            }
        }

        // write partials: Gs[kh][n][m]
        {
            int m0 = mh * 16 + (lane >> 2);
            int n0 = nh * 8 + (lane & 3) * 2;
            Gs[kh][n0][m0]         = acc[0];
            Gs[kh][n0 + 1][m0]     = acc[1];
            Gs[kh][n0][m0 + 8]     = acc[2];
            Gs[kh][n0 + 1][m0 + 8] = acc[3];
        }
        __syncthreads();

        // epilogue: kh=0 warps, thread (wu=w, lane=b)
        if (kh == 0) {
            float ai = Gs[0][w * 4 + 0][lane] + Gs[1][w * 4 + 0][lane] + bi;
            float af = Gs[0][w * 4 + 1][lane] + Gs[1][w * 4 + 1][lane] + bf_;
            float am = Gs[0][w * 4 + 2][lane] + Gs[1][w * 4 + 2][lane] + bm;
            float ao = Gs[0][w * 4 + 3][lane] + Gs[1][w * 4 + 3][lane] + bo;

            float gi = __saturatef(0.2f * ai + 0.5f);
            float gf = __saturatef(0.2f * af + 0.5f);
            float gm = fast_tanh(am);
            float go = __saturatef(0.2f * ao + 0.5f);
            c_state = gf * c_state + gi * gm;
            float h = go * fast_tanh(c_state);

            const int u = u0 + w;
            __nv_bfloat16 hh = __float2bfloat16_rn(h);
            __nv_bfloat16 hl = __float2bfloat16_rn(h - __bfloat162float(hh));
            size_t hb = (((size_t)t * 2 + dir) * 2) * 8192 + (size_t)u * 32 + lane;
            g_hbf[hb]        = hh;
            g_hbf[hb + 8192] = hl;
        }

        // ---- per-direction grid barrier (R5: single counter + backoff poll)
        __syncthreads();
        if (tid == 0) {
            asm volatile("red.release.gpu.global.add.u32 [%0], 1;" :: "l"(cnt) : "memory");
            const unsigned target = (unsigned)(s + 1) * 64u;
            unsigned v;
            asm volatile("ld.acquire.gpu.global.u32 %0, [%1];" : "=r"(v) : "l"(cnt) : "memory");
            while (v < target) {
                __nanosleep(32);
                asm volatile("ld.acquire.gpu.global.u32 %0, [%1];" : "=r"(v) : "l"(cnt) : "memory");
            }
        }
        __syncthreads();
        tprev = t;
    }
}

// ---------------- final transpose: out[b][t][c] = hh+hl from g_hbf -----------
__global__ void __launch_bounds__(256) transpose_out(float* __restrict__ out) {
    __shared__ float S[128 * 33];
    const int t  = blockIdx.x;
    const int c0 = blockIdx.y * 128;
    const int tid = threadIdx.x;
    const int dir = c0 >> 8;
    const int ub  = c0 & 255;          // 0 or 128

    const __nv_bfloat16* baseH = g_hbf
        + (((size_t)t * 2 + dir) * 2 + 0) * 8192 + (size_t)ub * 32;
    const __nv_bfloat16* baseL = baseH + 8192;

#pragma unroll
    for (int i = 0; i < 2; i++) {
        int c8 = tid + i * 256;          // 0..511 chunks of 8 halves
        int e  = c8 * 8;
        uint4 vh = *(const uint4*)(baseH + e);
        uint4 vl = *(const uint4*)(baseL + e);
        int u = e >> 5, b0 = e & 31;
        const uint32_t* ph = (const uint32_t*)&vh;
        const uint32_t* pl = (const uint32_t*)&vl;
        float* d = &S[u * 33 + b0];
#pragma unroll
        for (int j = 0; j < 4; j++) {
            __nv_bfloat162 h2 = *(__nv_bfloat162*)&ph[j];
            __nv_bfloat162 l2 = *(__nv_bfloat162*)&pl[j];
            float2 hf = __bfloat1622float2(h2);
            float2 lf = __bfloat1622float2(l2);
            d[j * 2]     = hf.x + lf.x;
            d[j * 2 + 1] = hf.y + lf.y;
        }
    }
    __syncthreads();

    const int lane = tid & 31;
    const int bq   = tid >> 5;
#pragma unroll
    for (int i = 0; i < 4; i++) {
        int b = bq + i * 8;
        int cc = lane * 4;
        float4 v = make_float4(S[(cc + 0) * 33 + b], S[(cc + 1) * 33 + b],
                               S[(cc + 2) * 33 + b], S[(cc + 3) * 33 + b]);
        *(float4*)&out[((size_t)b * TSEQ + t) * 512 + c0 + cc] = v;
    }
}

// ---------------- entry ------------------------------------------------------
extern "C" void kernel_launch(void* const* d_in, const int* in_sizes, int n_in,
                              void* d_out, int out_size) {
    (void)in_sizes; (void)n_in; (void)out_size;
    const float* x    = (const float*)d_in[0];   // [32,1024,256]
    const float* kern = (const float*)d_in[1];   // [256,2048]
    const float* rk   = (const float*)d_in[2];   // [256,2048]
    float* out = (float*)d_out;                  // [32,1024,512]

    dim3 pxgrid(TSEQ / 4, BATCH);                // (256, 32)
    prep_x<<<pxgrid, 256>>>(x);
    dim3 pwgrid(GC / 32, DIN / 32);              // (64, 8)
    prep_w<<<pwgrid, 256>>>(kern);
    dim3 ggrid(GC / 128, (BATCH * TSEQ) / 128);  // (16, 256)
    gemm_mma<<<ggrid, 256>>>(x, kern);
    blstm_rec<<<128, 256>>>(rk);
    dim3 tgrid(TSEQ, 4);
    transpose_out<<<tgrid, 256>>>(out);
}